// round 3
// baseline (speedup 1.0000x reference)
#include <cuda_runtime.h>

#define D_MODEL 1024
#define N_HEADS 16
#define D_HEAD  64
#define BATCH   4
#define SEQ     2048
#define M_TOK   (BATCH * SEQ)     /* 8192 */
#define D3      (3 * D_MODEL)     /* 3072 */

// Scratch (device globals: allocation-free per harness rules)
__device__ float g_qkv[(size_t)M_TOK * D3];       // 96 MB: [tok, 3*D] (q|k|v)
__device__ float g_attn[(size_t)M_TOK * D_MODEL]; // 32 MB: attention output [tok, D]

// ---------------------------------------------------------------------------
// SGEMM: C[M,N] = A[M,K] @ B[K,N], row-major, M%128==0, N%128==0, K%8==0
// 128x128 tile, BK=8, 256 threads, 8x8 register microtile.
// ---------------------------------------------------------------------------
__global__ __launch_bounds__(256)
void sgemm_kernel(const float* __restrict__ A, const float* __restrict__ B,
                  float* __restrict__ C, int M, int N, int K) {
    __shared__ float As[8][128];
    __shared__ float Bs[8][128];

    const int tid = threadIdx.x;
    const int tr  = tid / 16;          // 0..15  (row group)
    const int tc  = tid % 16;          // 0..15  (col group)
    const int rowBase = blockIdx.y * 128;
    const int colBase = blockIdx.x * 128;

    // A-tile load mapping: 128 rows x 8 k, float4 along K
    const int aRow = tid >> 1;            // 0..127
    const int aCol = (tid & 1) << 2;      // 0 or 4
    // B-tile load mapping: 8 k x 128 cols, float4 along N
    const int bRow = tid >> 5;            // 0..7
    const int bCol = (tid & 31) << 2;     // 0..124

    float acc[8][8];
    #pragma unroll
    for (int i = 0; i < 8; i++)
        #pragma unroll
        for (int j = 0; j < 8; j++) acc[i][j] = 0.f;

    for (int k0 = 0; k0 < K; k0 += 8) {
        float4 a = *(const float4*)&A[(size_t)(rowBase + aRow) * K + k0 + aCol];
        As[aCol + 0][aRow] = a.x;
        As[aCol + 1][aRow] = a.y;
        As[aCol + 2][aRow] = a.z;
        As[aCol + 3][aRow] = a.w;
        *(float4*)&Bs[bRow][bCol] =
            *(const float4*)&B[(size_t)(k0 + bRow) * N + colBase + bCol];
        __syncthreads();

        #pragma unroll
        for (int k = 0; k < 8; k++) {
            float ar[8], br[8];
            #pragma unroll
            for (int i = 0; i < 8; i++) ar[i] = As[k][tr * 8 + i];
            #pragma unroll
            for (int j = 0; j < 8; j++) br[j] = Bs[k][tc * 8 + j];
            #pragma unroll
            for (int i = 0; i < 8; i++)
                #pragma unroll
                for (int j = 0; j < 8; j++) acc[i][j] += ar[i] * br[j];
        }
        __syncthreads();
    }

    #pragma unroll
    for (int i = 0; i < 8; i++) {
        float* cp = &C[(size_t)(rowBase + tr * 8 + i) * N + colBase + tc * 8];
        float4 v0 = make_float4(acc[i][0], acc[i][1], acc[i][2], acc[i][3]);
        float4 v1 = make_float4(acc[i][4], acc[i][5], acc[i][6], acc[i][7]);
        *(float4*)(cp + 0) = v0;
        *(float4*)(cp + 4) = v1;
    }
}

// ---------------------------------------------------------------------------
// Flash attention, fp32. One thread owns one query row (q + accumulator in
// registers). KV tiles of 32 rows staged in SMEM; Ks/Vs reads are warp
// broadcasts (all lanes process the same key j) so the loop is FFMA-bound.
// Per-thread score row lives in padded SMEM (stride 33 -> conflict-free).
// Grid: (SEQ/128, N_HEADS, BATCH), block 128.
// ---------------------------------------------------------------------------
__global__ __launch_bounds__(128)
void attn_kernel(float* __restrict__ attn_out) {
    __shared__ float Ks[32][64];
    __shared__ float Vs[32][64];
    __shared__ float Ss[128][33];

    const int tid = threadIdx.x;
    const int b   = blockIdx.z;
    const int h   = blockIdx.y;
    const int qrow = blockIdx.x * 128 + tid;      // token within sequence
    const float scale = 0.125f;                    // 1/sqrt(64)

    const float* qptr = g_qkv + (size_t)(b * SEQ + qrow) * D3 + h * D_HEAD;

    float q[64];
    #pragma unroll
    for (int d = 0; d < 64; d += 4) {
        float4 v4 = *(const float4*)(qptr + d);
        q[d] = v4.x; q[d + 1] = v4.y; q[d + 2] = v4.z; q[d + 3] = v4.w;
    }

    float accO[64];
    #pragma unroll
    for (int d = 0; d < 64; d++) accO[d] = 0.f;
    float m = -1e30f, l = 0.f;

    float* srow = Ss[tid];

    for (int kt = 0; kt < SEQ; kt += 32) {
        // Stage K/V tile: 32 rows x 64 floats each; 16 lanes cover one row
        // (4 x float4) -> fully coalesced 256B segments.
        for (int u = tid; u < 32 * 16; u += 128) {
            int r = u >> 4;
            int c = (u & 15) << 2;
            const float* base = g_qkv + (size_t)(b * SEQ + kt + r) * D3 + h * D_HEAD + c;
            *(float4*)&Ks[r][c] = *(const float4*)(base + D_MODEL);
            *(float4*)&Vs[r][c] = *(const float4*)(base + 2 * D_MODEL);
        }
        __syncthreads();

        // S = scale * q . K_j  (4 partial sums for ILP)
        for (int j = 0; j < 32; j++) {
            float s0 = 0.f, s1 = 0.f, s2 = 0.f, s3 = 0.f;
            #pragma unroll
            for (int d = 0; d < 64; d += 4) {
                s0 += q[d + 0] * Ks[j][d + 0];
                s1 += q[d + 1] * Ks[j][d + 1];
                s2 += q[d + 2] * Ks[j][d + 2];
                s3 += q[d + 3] * Ks[j][d + 3];
            }
            srow[j] = scale * ((s0 + s1) + (s2 + s3));
        }

        // Online softmax update
        float tmax = srow[0];
        #pragma unroll
        for (int j = 1; j < 32; j++) tmax = fmaxf(tmax, srow[j]);
        float mn = fmaxf(m, tmax);
        float corr = __expf(m - mn);
        l *= corr;
        #pragma unroll
        for (int d = 0; d < 64; d++) accO[d] *= corr;

        for (int j = 0; j < 32; j++) {
            float p = __expf(srow[j] - mn);
            l += p;
            #pragma unroll
            for (int d = 0; d < 64; d++) accO[d] += p * Vs[j][d];
        }
        m = mn;
        __syncthreads();
    }

    const float inv = 1.f / l;
    float* optr = g_attn + (size_t)(b * SEQ + qrow) * D_MODEL + h * D_HEAD;
    #pragma unroll
    for (int d = 0; d < 64; d += 4) {
        float4 v4 = make_float4(accO[d] * inv, accO[d + 1] * inv,
                                accO[d + 2] * inv, accO[d + 3] * inv);
        *(float4*)(optr + d) = v4;
    }
}

// dummy arg so attn_kernel signature stays stable
extern "C" void kernel_launch(void* const* d_in, const int* in_sizes, int n_in,
                              void* d_out, int out_size) {
    const float* x      = (const float*)d_in[0];  // [4,2048,1024]
    const float* w_qkv  = (const float*)d_in[1];  // [1024,3072]
    const float* w_proj = (const float*)d_in[2];  // [1024,1024]
    float* out = (float*)d_out;                   // [4,2048,1024]

    float *qkv_ptr = nullptr, *attn_ptr = nullptr;
    cudaGetSymbolAddress((void**)&qkv_ptr, g_qkv);
    cudaGetSymbolAddress((void**)&attn_ptr, g_attn);

    // 1) QKV = X @ W_qkv  -> g_qkv [8192, 3072]
    sgemm_kernel<<<dim3(D3 / 128, M_TOK / 128), 256>>>(
        x, w_qkv, qkv_ptr, M_TOK, D3, D_MODEL);

    // 2) Flash attention -> g_attn [8192, 1024]
    attn_kernel<<<dim3(SEQ / 128, N_HEADS, BATCH), 128>>>(attn_ptr);

    // 3) Out = attn @ W_proj -> d_out
    sgemm_kernel<<<dim3(D_MODEL / 128, M_TOK / 128), 256>>>(
        attn_ptr, w_proj, out, M_TOK, D_MODEL, D_MODEL);
}

// round 7
// speedup vs baseline: 1.3899x; 1.3899x over previous
#include <cuda_runtime.h>
#include <cstdint>

#define D_MODEL 1024
#define N_HEADS 16
#define D_HEAD  64
#define BATCH   4
#define SEQ     2048
#define M_TOK   (BATCH * SEQ)     /* 8192 */
#define D3      (3 * D_MODEL)     /* 3072 */

// Scratch (device globals: allocation-free per harness rules)
__device__ float g_qkv[(size_t)M_TOK * D3];       // 96 MB: [tok, 3*D] (q|k|v)
__device__ float g_attn[(size_t)M_TOK * D_MODEL]; // 32 MB: attention output [tok, D]

__device__ __forceinline__ uint32_t f2tf(float f) {
    uint32_t u;
    asm("cvt.rna.tf32.f32 %0, %1;" : "=r"(u) : "f"(f));
    return u;
}

// ---------------------------------------------------------------------------
// TF32 tensor-core GEMM: C[M,N] = A[M,K] @ B[K,N], row-major.
// Block tile 128x128, BK=16, 256 threads (8 warps, 2x4), warp tile 64x32.
// Double-buffered SMEM; fp32->tf32 conversion fused into staging.
// SMEM bank analysis: As stride 20 (== 4 mod 32) -> A-frag LDS conflict-free;
// Bs stride 136 (== 8 mod 32) -> B-frag LDS conflict-free.
// ---------------------------------------------------------------------------
#define BM 128
#define BN 128
#define BKT 16
#define ASTRIDE (BKT + 4)   /* 20 */
#define BSTRIDE (BN + 8)    /* 136 */

__global__ __launch_bounds__(256)
void gemm_tf32(const float* __restrict__ A, const float* __restrict__ B,
               float* __restrict__ C, int M, int N, int K) {
    __shared__ uint32_t As[2][BM * ASTRIDE];   // [m][k], tf32 bits
    __shared__ uint32_t Bs[2][BKT * BSTRIDE];  // [k][n], tf32 bits

    const int tid   = threadIdx.x;
    const int warp  = tid >> 5;
    const int lane  = tid & 31;
    const int wm    = warp >> 2;        // 0..1
    const int wn    = warp & 3;         // 0..3
    const int group = lane >> 2;        // 0..7
    const int tig   = lane & 3;         // 0..3
    const int rowBase = blockIdx.y * BM;
    const int colBase = blockIdx.x * BN;
    const int mBase = wm * 64;
    const int nBase = wn * 32;

    float4 ra[2], rb[2];

    float acc[4][4][4];
    #pragma unroll
    for (int mi = 0; mi < 4; mi++)
        #pragma unroll
        for (int ni = 0; ni < 4; ni++)
            #pragma unroll
            for (int r = 0; r < 4; r++) acc[mi][ni][r] = 0.f;

    const int T = K / BKT;

    // ---- prologue: load tile 0 ----
    #pragma unroll
    for (int i = 0; i < 2; i++) {
        int u = tid + 256 * i;
        int r = u >> 2, c = (u & 3) << 2;
        ra[i] = *(const float4*)&A[(size_t)(rowBase + r) * K + c];
        int br = u >> 5, bc = (u & 31) << 2;
        rb[i] = *(const float4*)&B[(size_t)br * N + colBase + bc];
    }
    #pragma unroll
    for (int i = 0; i < 2; i++) {
        int u = tid + 256 * i;
        int r = u >> 2, c = (u & 3) << 2;
        uint32_t* p = &As[0][r * ASTRIDE + c];
        p[0] = f2tf(ra[i].x); p[1] = f2tf(ra[i].y);
        p[2] = f2tf(ra[i].z); p[3] = f2tf(ra[i].w);
        int br = u >> 5, bc = (u & 31) << 2;
        uint32_t* q = &Bs[0][br * BSTRIDE + bc];
        q[0] = f2tf(rb[i].x); q[1] = f2tf(rb[i].y);
        q[2] = f2tf(rb[i].z); q[3] = f2tf(rb[i].w);
    }

    for (int t = 0; t < T; t++) {
        __syncthreads();
        const int buf = t & 1;

        // prefetch next tile (global -> regs) while computing current
        if (t + 1 < T) {
            const int kt = (t + 1) * BKT;
            #pragma unroll
            for (int i = 0; i < 2; i++) {
                int u = tid + 256 * i;
                int r = u >> 2, c = (u & 3) << 2;
                ra[i] = *(const float4*)&A[(size_t)(rowBase + r) * K + kt + c];
                int br = u >> 5, bc = (u & 31) << 2;
                rb[i] = *(const float4*)&B[(size_t)(kt + br) * N + colBase + bc];
            }
        }

        // ---- compute on buf ----
        #pragma unroll
        for (int ks = 0; ks < 2; ks++) {
            const int k0 = ks * 8;
            uint32_t a[4][4];
            #pragma unroll
            for (int mi = 0; mi < 4; mi++) {
                int r0 = mBase + mi * 16 + group;
                a[mi][0] = As[buf][(r0    ) * ASTRIDE + k0 + tig    ];
                a[mi][1] = As[buf][(r0 + 8) * ASTRIDE + k0 + tig    ];
                a[mi][2] = As[buf][(r0    ) * ASTRIDE + k0 + tig + 4];
                a[mi][3] = As[buf][(r0 + 8) * ASTRIDE + k0 + tig + 4];
            }
            #pragma unroll
            for (int ni = 0; ni < 4; ni++) {
                uint32_t b0 = Bs[buf][(k0 + tig    ) * BSTRIDE + nBase + ni * 8 + group];
                uint32_t b1 = Bs[buf][(k0 + tig + 4) * BSTRIDE + nBase + ni * 8 + group];
                #pragma unroll
                for (int mi = 0; mi < 4; mi++) {
                    asm volatile(
                        "mma.sync.aligned.m16n8k8.row.col.f32.tf32.tf32.f32 "
                        "{%0,%1,%2,%3}, {%4,%5,%6,%7}, {%8,%9}, {%0,%1,%2,%3};"
                        : "+f"(acc[mi][ni][0]), "+f"(acc[mi][ni][1]),
                          "+f"(acc[mi][ni][2]), "+f"(acc[mi][ni][3])
                        : "r"(a[mi][0]), "r"(a[mi][1]), "r"(a[mi][2]), "r"(a[mi][3]),
                          "r"(b0), "r"(b1));
                }
            }
        }

        // stage prefetched tile into the other buffer
        if (t + 1 < T) {
            const int nbuf = buf ^ 1;
            #pragma unroll
            for (int i = 0; i < 2; i++) {
                int u = tid + 256 * i;
                int r = u >> 2, c = (u & 3) << 2;
                uint32_t* p = &As[nbuf][r * ASTRIDE + c];
                p[0] = f2tf(ra[i].x); p[1] = f2tf(ra[i].y);
                p[2] = f2tf(ra[i].z); p[3] = f2tf(ra[i].w);
                int br = u >> 5, bc = (u & 31) << 2;
                uint32_t* q = &Bs[nbuf][br * BSTRIDE + bc];
                q[0] = f2tf(rb[i].x); q[1] = f2tf(rb[i].y);
                q[2] = f2tf(rb[i].z); q[3] = f2tf(rb[i].w);
            }
        }
    }

    // ---- epilogue ----
    #pragma unroll
    for (int mi = 0; mi < 4; mi++) {
        int r0 = rowBase + mBase + mi * 16 + group;
        #pragma unroll
        for (int ni = 0; ni < 4; ni++) {
            int cc = colBase + nBase + ni * 8 + tig * 2;
            *(float2*)&C[(size_t)r0 * N + cc] =
                make_float2(acc[mi][ni][0], acc[mi][ni][1]);
            *(float2*)&C[(size_t)(r0 + 8) * N + cc] =
                make_float2(acc[mi][ni][2], acc[mi][ni][3]);
        }
    }
}

// ---------------------------------------------------------------------------
// Flash attention, fp32 (unchanged from R3 — R5 target for tensorization).
// One thread owns one query row; KV tiles of 32 staged in SMEM.
// ---------------------------------------------------------------------------
__global__ __launch_bounds__(128)
void attn_kernel(float* __restrict__ attn_out) {
    __shared__ float Ks[32][64];
    __shared__ float Vs[32][64];
    __shared__ float Ss[128][33];

    const int tid = threadIdx.x;
    const int b   = blockIdx.z;
    const int h   = blockIdx.y;
    const int qrow = blockIdx.x * 128 + tid;
    const float scale = 0.125f;

    const float* qptr = g_qkv + (size_t)(b * SEQ + qrow) * D3 + h * D_HEAD;

    float q[64];
    #pragma unroll
    for (int d = 0; d < 64; d += 4) {
        float4 v4 = *(const float4*)(qptr + d);
        q[d] = v4.x; q[d + 1] = v4.y; q[d + 2] = v4.z; q[d + 3] = v4.w;
    }

    float accO[64];
    #pragma unroll
    for (int d = 0; d < 64; d++) accO[d] = 0.f;
    float m = -1e30f, l = 0.f;

    float* srow = Ss[tid];

    for (int kt = 0; kt < SEQ; kt += 32) {
        for (int u = tid; u < 32 * 16; u += 128) {
            int r = u >> 4;
            int c = (u & 15) << 2;
            const float* base = g_qkv + (size_t)(b * SEQ + kt + r) * D3 + h * D_HEAD + c;
            *(float4*)&Ks[r][c] = *(const float4*)(base + D_MODEL);
            *(float4*)&Vs[r][c] = *(const float4*)(base + 2 * D_MODEL);
        }
        __syncthreads();

        for (int j = 0; j < 32; j++) {
            float s0 = 0.f, s1 = 0.f, s2 = 0.f, s3 = 0.f;
            #pragma unroll
            for (int d = 0; d < 64; d += 4) {
                s0 += q[d + 0] * Ks[j][d + 0];
                s1 += q[d + 1] * Ks[j][d + 1];
                s2 += q[d + 2] * Ks[j][d + 2];
                s3 += q[d + 3] * Ks[j][d + 3];
            }
            srow[j] = scale * ((s0 + s1) + (s2 + s3));
        }

        float tmax = srow[0];
        #pragma unroll
        for (int j = 1; j < 32; j++) tmax = fmaxf(tmax, srow[j]);
        float mn = fmaxf(m, tmax);
        float corr = __expf(m - mn);
        l *= corr;
        #pragma unroll
        for (int d = 0; d < 64; d++) accO[d] *= corr;

        for (int j = 0; j < 32; j++) {
            float p = __expf(srow[j] - mn);
            l += p;
            #pragma unroll
            for (int d = 0; d < 64; d++) accO[d] += p * Vs[j][d];
        }
        m = mn;
        __syncthreads();
    }

    const float inv = 1.f / l;
    float* optr = g_attn + (size_t)(b * SEQ + qrow) * D_MODEL + h * D_HEAD;
    #pragma unroll
    for (int d = 0; d < 64; d += 4) {
        float4 v4 = make_float4(accO[d] * inv, accO[d + 1] * inv,
                                accO[d + 2] * inv, accO[d + 3] * inv);
        *(float4*)(optr + d) = v4;
    }
}

extern "C" void kernel_launch(void* const* d_in, const int* in_sizes, int n_in,
                              void* d_out, int out_size) {
    const float* x      = (const float*)d_in[0];  // [4,2048,1024]
    const float* w_qkv  = (const float*)d_in[1];  // [1024,3072]
    const float* w_proj = (const float*)d_in[2];  // [1024,1024]
    float* out = (float*)d_out;                   // [4,2048,1024]

    float *qkv_ptr = nullptr, *attn_ptr = nullptr;
    cudaGetSymbolAddress((void**)&qkv_ptr, g_qkv);
    cudaGetSymbolAddress((void**)&attn_ptr, g_attn);

    // 1) QKV = X @ W_qkv  -> g_qkv [8192, 3072]   (tensor cores, tf32)
    gemm_tf32<<<dim3(D3 / BN, M_TOK / BM), 256>>>(
        x, w_qkv, qkv_ptr, M_TOK, D3, D_MODEL);

    // 2) Flash attention -> g_attn [8192, 1024]   (fp32)
    attn_kernel<<<dim3(SEQ / 128, N_HEADS, BATCH), 128>>>(attn_ptr);

    // 3) Out = attn @ W_proj -> d_out             (tensor cores, tf32)
    gemm_tf32<<<dim3(D_MODEL / BN, M_TOK / BM), 256>>>(
        attn_ptr, w_proj, out, M_TOK, D_MODEL, D_MODEL);
}

// round 11
// speedup vs baseline: 3.2237x; 2.3194x over previous
#include <cuda_runtime.h>
#include <cstdint>

#define D_MODEL 1024
#define N_HEADS 16
#define D_HEAD  64
#define BATCH   4
#define SEQ     2048
#define M_TOK   (BATCH * SEQ)     /* 8192 */
#define D3      (3 * D_MODEL)     /* 3072 */

// Scratch (device globals: allocation-free per harness rules)
__device__ float g_qkv[(size_t)M_TOK * D3];       // 96 MB: [tok, 3*D] (q|k|v)
__device__ float g_attn[(size_t)M_TOK * D_MODEL]; // 32 MB: attention output [tok, D]

__device__ __forceinline__ uint32_t f2tf(float f) {
    uint32_t u;
    asm("cvt.rna.tf32.f32 %0, %1;" : "=r"(u) : "f"(f));
    return u;
}

__device__ __forceinline__ void mma_tf32(float* c, const uint32_t* a,
                                         uint32_t b0, uint32_t b1) {
    asm volatile(
        "mma.sync.aligned.m16n8k8.row.col.f32.tf32.tf32.f32 "
        "{%0,%1,%2,%3}, {%4,%5,%6,%7}, {%8,%9}, {%0,%1,%2,%3};"
        : "+f"(c[0]), "+f"(c[1]), "+f"(c[2]), "+f"(c[3])
        : "r"(a[0]), "r"(a[1]), "r"(a[2]), "r"(a[3]), "r"(b0), "r"(b1));
}

// ---------------------------------------------------------------------------
// TF32 tensor-core GEMM (unchanged from R7): C = A @ B, 128x128x16 tiles.
// ---------------------------------------------------------------------------
#define BM 128
#define BN 128
#define BKT 16
#define ASTRIDE (BKT + 4)   /* 20 */
#define BSTRIDE (BN + 8)    /* 136 */

__global__ __launch_bounds__(256)
void gemm_tf32(const float* __restrict__ A, const float* __restrict__ B,
               float* __restrict__ C, int M, int N, int K) {
    __shared__ uint32_t As[2][BM * ASTRIDE];
    __shared__ uint32_t Bs[2][BKT * BSTRIDE];

    const int tid   = threadIdx.x;
    const int warp  = tid >> 5;
    const int lane  = tid & 31;
    const int wm    = warp >> 2;
    const int wn    = warp & 3;
    const int group = lane >> 2;
    const int tig   = lane & 3;
    const int rowBase = blockIdx.y * BM;
    const int colBase = blockIdx.x * BN;
    const int mBase = wm * 64;
    const int nBase = wn * 32;

    float4 ra[2], rb[2];

    float acc[4][4][4];
    #pragma unroll
    for (int mi = 0; mi < 4; mi++)
        #pragma unroll
        for (int ni = 0; ni < 4; ni++)
            #pragma unroll
            for (int r = 0; r < 4; r++) acc[mi][ni][r] = 0.f;

    const int T = K / BKT;

    #pragma unroll
    for (int i = 0; i < 2; i++) {
        int u = tid + 256 * i;
        int r = u >> 2, c = (u & 3) << 2;
        ra[i] = *(const float4*)&A[(size_t)(rowBase + r) * K + c];
        int br = u >> 5, bc = (u & 31) << 2;
        rb[i] = *(const float4*)&B[(size_t)br * N + colBase + bc];
    }
    #pragma unroll
    for (int i = 0; i < 2; i++) {
        int u = tid + 256 * i;
        int r = u >> 2, c = (u & 3) << 2;
        uint32_t* p = &As[0][r * ASTRIDE + c];
        p[0] = f2tf(ra[i].x); p[1] = f2tf(ra[i].y);
        p[2] = f2tf(ra[i].z); p[3] = f2tf(ra[i].w);
        int br = u >> 5, bc = (u & 31) << 2;
        uint32_t* q = &Bs[0][br * BSTRIDE + bc];
        q[0] = f2tf(rb[i].x); q[1] = f2tf(rb[i].y);
        q[2] = f2tf(rb[i].z); q[3] = f2tf(rb[i].w);
    }

    for (int t = 0; t < T; t++) {
        __syncthreads();
        const int buf = t & 1;

        if (t + 1 < T) {
            const int kt = (t + 1) * BKT;
            #pragma unroll
            for (int i = 0; i < 2; i++) {
                int u = tid + 256 * i;
                int r = u >> 2, c = (u & 3) << 2;
                ra[i] = *(const float4*)&A[(size_t)(rowBase + r) * K + kt + c];
                int br = u >> 5, bc = (u & 31) << 2;
                rb[i] = *(const float4*)&B[(size_t)(kt + br) * N + colBase + bc];
            }
        }

        #pragma unroll
        for (int ks = 0; ks < 2; ks++) {
            const int k0 = ks * 8;
            uint32_t a[4][4];
            #pragma unroll
            for (int mi = 0; mi < 4; mi++) {
                int r0 = mBase + mi * 16 + group;
                a[mi][0] = As[buf][(r0    ) * ASTRIDE + k0 + tig    ];
                a[mi][1] = As[buf][(r0 + 8) * ASTRIDE + k0 + tig    ];
                a[mi][2] = As[buf][(r0    ) * ASTRIDE + k0 + tig + 4];
                a[mi][3] = As[buf][(r0 + 8) * ASTRIDE + k0 + tig + 4];
            }
            #pragma unroll
            for (int ni = 0; ni < 4; ni++) {
                uint32_t b0 = Bs[buf][(k0 + tig    ) * BSTRIDE + nBase + ni * 8 + group];
                uint32_t b1 = Bs[buf][(k0 + tig + 4) * BSTRIDE + nBase + ni * 8 + group];
                #pragma unroll
                for (int mi = 0; mi < 4; mi++)
                    mma_tf32(acc[mi][ni], a[mi], b0, b1);
            }
        }

        if (t + 1 < T) {
            const int nbuf = buf ^ 1;
            #pragma unroll
            for (int i = 0; i < 2; i++) {
                int u = tid + 256 * i;
                int r = u >> 2, c = (u & 3) << 2;
                uint32_t* p = &As[nbuf][r * ASTRIDE + c];
                p[0] = f2tf(ra[i].x); p[1] = f2tf(ra[i].y);
                p[2] = f2tf(ra[i].z); p[3] = f2tf(ra[i].w);
                int br = u >> 5, bc = (u & 31) << 2;
                uint32_t* q = &Bs[nbuf][br * BSTRIDE + bc];
                q[0] = f2tf(rb[i].x); q[1] = f2tf(rb[i].y);
                q[2] = f2tf(rb[i].z); q[3] = f2tf(rb[i].w);
            }
        }
    }

    #pragma unroll
    for (int mi = 0; mi < 4; mi++) {
        int r0 = rowBase + mBase + mi * 16 + group;
        #pragma unroll
        for (int ni = 0; ni < 4; ni++) {
            int cc = colBase + nBase + ni * 8 + tig * 2;
            *(float2*)&C[(size_t)r0 * N + cc] =
                make_float2(acc[mi][ni][0], acc[mi][ni][1]);
            *(float2*)&C[(size_t)(r0 + 8) * N + cc] =
                make_float2(acc[mi][ni][2], acc[mi][ni][3]);
        }
    }
}

// ---------------------------------------------------------------------------
// TF32 tensor-core flash attention.
// Grid (SEQ/128, H, B); 256 threads / 8 warps. Warp owns 16 query rows.
// K-tile = 64 keys. S = Q@K^T and O += P@V via m16n8k8 TF32 mma.
// Softmax in fp32 on fragments; P goes through a warp-private SMEM slab
// (tf32) to re-shape C-frag -> A-frag layout (only __syncwarp needed).
// SMEM (dynamic, 70 KB): Kt[64][68] | Vt[64][68] | QP[128][72]
//   stride 68 == 4 (mod 32)  -> S/PV B-frag loads conflict-free
//   stride 72 == 8 (mod 32)  -> P A-frag loads max 2-way
// K is pre-scaled by 0.125 (exact pow2) during staging -> no S scaling op.
// ---------------------------------------------------------------------------
#define KT_W   (64 * 68)
#define QP_OFF (2 * KT_W)
#define ATT_SMEM_BYTES ((2 * KT_W + 128 * 72) * 4)   /* 71680 */

__global__ __launch_bounds__(256)
void attn_tc_kernel() {
    extern __shared__ uint32_t smem[];
    uint32_t* Kt = smem;
    uint32_t* Vt = smem + KT_W;
    uint32_t* QP = smem + QP_OFF;          // Q staging, then P slabs

    const int tid   = threadIdx.x;
    const int warp  = tid >> 5;
    const int lane  = tid & 31;
    const int group = lane >> 2;           // 0..7
    const int tig   = lane & 3;            // 0..3
    const int b     = blockIdx.z;
    const int h     = blockIdx.y;
    const int q0    = blockIdx.x * 128;

    // ---- stage Q tile [128][64] -> QP (f32, stride 72), coalesced ----
    {
        float* Qf = (float*)QP;
        #pragma unroll
        for (int i = 0; i < 8; i++) {
            int u = tid + 256 * i;
            int r = u >> 4, c = (u & 15) << 2;
            float4 v4 = *(const float4*)&g_qkv[(size_t)(b * SEQ + q0 + r) * D3 + h * D_HEAD + c];
            *(float4*)&Qf[r * 72 + c] = v4;
        }
    }
    __syncthreads();

    // ---- read Q fragments into registers (tf32), warp-local rows ----
    uint32_t qa[8][4];
    {
        const float* Qf = (const float*)QP;
        const int r0 = warp * 16 + group;
        #pragma unroll
        for (int ks = 0; ks < 8; ks++) {
            qa[ks][0] = f2tf(Qf[(r0    ) * 72 + ks * 8 + tig    ]);
            qa[ks][1] = f2tf(Qf[(r0 + 8) * 72 + ks * 8 + tig    ]);
            qa[ks][2] = f2tf(Qf[(r0    ) * 72 + ks * 8 + tig + 4]);
            qa[ks][3] = f2tf(Qf[(r0 + 8) * 72 + ks * 8 + tig + 4]);
        }
    }

    uint32_t* Pw = QP + warp * 16 * 72;    // this warp's P slab [16][72]

    float oacc[8][4];
    #pragma unroll
    for (int nf = 0; nf < 8; nf++)
        #pragma unroll
        for (int j = 0; j < 4; j++) oacc[nf][j] = 0.f;
    float m0 = -1e30f, m1 = -1e30f, l0 = 0.f, l1 = 0.f;

    for (int kt = 0; kt < SEQ; kt += 64) {
        // ---- stage K (scaled), V tiles: [64][64] -> tf32, stride 68 ----
        #pragma unroll
        for (int i = 0; i < 4; i++) {
            int u = tid + 256 * i;
            int r = u >> 4, c = (u & 15) << 2;
            const float* kb = &g_qkv[(size_t)(b * SEQ + kt + r) * D3 + D_MODEL + h * D_HEAD + c];
            float4 k4 = *(const float4*)kb;
            float4 v4 = *(const float4*)(kb + D_MODEL);
            uint32_t* kd = &Kt[r * 68 + c];
            kd[0] = f2tf(0.125f * k4.x); kd[1] = f2tf(0.125f * k4.y);
            kd[2] = f2tf(0.125f * k4.z); kd[3] = f2tf(0.125f * k4.w);
            uint32_t* vd = &Vt[r * 68 + c];
            vd[0] = f2tf(v4.x); vd[1] = f2tf(v4.y);
            vd[2] = f2tf(v4.z); vd[3] = f2tf(v4.w);
        }
        __syncthreads();

        // ---- S = Q @ K^T : warp tile 16 x 64 ----
        float sacc[8][4];
        #pragma unroll
        for (int nf = 0; nf < 8; nf++)
            #pragma unroll
            for (int j = 0; j < 4; j++) sacc[nf][j] = 0.f;

        #pragma unroll
        for (int ks = 0; ks < 8; ks++) {
            #pragma unroll
            for (int nf = 0; nf < 8; nf++) {
                uint32_t b0 = Kt[(nf * 8 + group) * 68 + ks * 8 + tig    ];
                uint32_t b1 = Kt[(nf * 8 + group) * 68 + ks * 8 + tig + 4];
                mma_tf32(sacc[nf], qa[ks], b0, b1);
            }
        }

        // ---- online softmax (fp32), rows group / group+8 ----
        float mx0 = -1e30f, mx1 = -1e30f;
        #pragma unroll
        for (int nf = 0; nf < 8; nf++) {
            mx0 = fmaxf(mx0, fmaxf(sacc[nf][0], sacc[nf][1]));
            mx1 = fmaxf(mx1, fmaxf(sacc[nf][2], sacc[nf][3]));
        }
        mx0 = fmaxf(mx0, __shfl_xor_sync(0xffffffffu, mx0, 1));
        mx0 = fmaxf(mx0, __shfl_xor_sync(0xffffffffu, mx0, 2));
        mx1 = fmaxf(mx1, __shfl_xor_sync(0xffffffffu, mx1, 1));
        mx1 = fmaxf(mx1, __shfl_xor_sync(0xffffffffu, mx1, 2));

        float mn0 = fmaxf(m0, mx0), mn1 = fmaxf(m1, mx1);
        float c0 = __expf(m0 - mn0), c1 = __expf(m1 - mn1);
        l0 *= c0; l1 *= c1;
        #pragma unroll
        for (int nf = 0; nf < 8; nf++) {
            oacc[nf][0] *= c0; oacc[nf][1] *= c0;
            oacc[nf][2] *= c1; oacc[nf][3] *= c1;
        }

        float ps0 = 0.f, ps1 = 0.f;
        #pragma unroll
        for (int nf = 0; nf < 8; nf++) {
            float p0 = __expf(sacc[nf][0] - mn0);
            float p1 = __expf(sacc[nf][1] - mn0);
            float p2 = __expf(sacc[nf][2] - mn1);
            float p3 = __expf(sacc[nf][3] - mn1);
            ps0 += p0 + p1; ps1 += p2 + p3;
            uint32_t* pr0 = &Pw[(group    ) * 72 + nf * 8 + tig * 2];
            uint32_t* pr1 = &Pw[(group + 8) * 72 + nf * 8 + tig * 2];
            pr0[0] = f2tf(p0); pr0[1] = f2tf(p1);
            pr1[0] = f2tf(p2); pr1[1] = f2tf(p3);
        }
        ps0 += __shfl_xor_sync(0xffffffffu, ps0, 1);
        ps0 += __shfl_xor_sync(0xffffffffu, ps0, 2);
        ps1 += __shfl_xor_sync(0xffffffffu, ps1, 1);
        ps1 += __shfl_xor_sync(0xffffffffu, ps1, 2);
        l0 += ps0; l1 += ps1;
        m0 = mn0; m1 = mn1;
        __syncwarp();

        // ---- O += P @ V ----
        #pragma unroll
        for (int ks = 0; ks < 8; ks++) {
            uint32_t pa[4];
            pa[0] = Pw[(group    ) * 72 + ks * 8 + tig    ];
            pa[1] = Pw[(group + 8) * 72 + ks * 8 + tig    ];
            pa[2] = Pw[(group    ) * 72 + ks * 8 + tig + 4];
            pa[3] = Pw[(group + 8) * 72 + ks * 8 + tig + 4];
            #pragma unroll
            for (int nf = 0; nf < 8; nf++) {
                uint32_t b0 = Vt[(ks * 8 + tig    ) * 68 + nf * 8 + group];
                uint32_t b1 = Vt[(ks * 8 + tig + 4) * 68 + nf * 8 + group];
                mma_tf32(oacc[nf], pa, b0, b1);
            }
        }
        __syncthreads();   // before next K/V overwrite
    }

    // ---- epilogue: normalize and store ----
    const float inv0 = 1.f / l0, inv1 = 1.f / l1;
    const int r0 = b * SEQ + q0 + warp * 16 + group;
    #pragma unroll
    for (int nf = 0; nf < 8; nf++) {
        int cc = h * D_HEAD + nf * 8 + tig * 2;
        *(float2*)&g_attn[(size_t)r0 * D_MODEL + cc] =
            make_float2(oacc[nf][0] * inv0, oacc[nf][1] * inv0);
        *(float2*)&g_attn[(size_t)(r0 + 8) * D_MODEL + cc] =
            make_float2(oacc[nf][2] * inv1, oacc[nf][3] * inv1);
    }
}

extern "C" void kernel_launch(void* const* d_in, const int* in_sizes, int n_in,
                              void* d_out, int out_size) {
    const float* x      = (const float*)d_in[0];  // [4,2048,1024]
    const float* w_qkv  = (const float*)d_in[1];  // [1024,3072]
    const float* w_proj = (const float*)d_in[2];  // [1024,1024]
    float* out = (float*)d_out;                   // [4,2048,1024]

    float *qkv_ptr = nullptr, *attn_ptr = nullptr;
    cudaGetSymbolAddress((void**)&qkv_ptr, g_qkv);
    cudaGetSymbolAddress((void**)&attn_ptr, g_attn);

    cudaFuncSetAttribute(attn_tc_kernel,
                         cudaFuncAttributeMaxDynamicSharedMemorySize,
                         ATT_SMEM_BYTES);

    // 1) QKV = X @ W_qkv  (tf32 mma)
    gemm_tf32<<<dim3(D3 / BN, M_TOK / BM), 256>>>(
        x, w_qkv, qkv_ptr, M_TOK, D3, D_MODEL);

    // 2) Flash attention (tf32 mma)
    attn_tc_kernel<<<dim3(SEQ / 128, N_HEADS, BATCH), 256, ATT_SMEM_BYTES>>>();

    // 3) Out = attn @ W_proj (tf32 mma)
    gemm_tf32<<<dim3(D_MODEL / BN, M_TOK / BM), 256>>>(
        attn_ptr, w_proj, out, M_TOK, D_MODEL, D_MODEL);
}

// round 14
// speedup vs baseline: 3.7459x; 1.1620x over previous
#include <cuda_runtime.h>
#include <cstdint>

#define D_MODEL 1024
#define N_HEADS 16
#define D_HEAD  64
#define BATCH   4
#define SEQ     2048
#define M_TOK   (BATCH * SEQ)     /* 8192 */
#define D3      (3 * D_MODEL)     /* 3072 */

// Scratch (device globals: allocation-free per harness rules)
__device__ float g_qkv[(size_t)M_TOK * D3];        // 96 MB, tf32-rounded
__device__ float g_attn[(size_t)M_TOK * D_MODEL];  // 32 MB, tf32-rounded
__device__ float g_xr[(size_t)M_TOK * D_MODEL];    // 32 MB, tf32-rounded x
__device__ float g_wq[(size_t)D_MODEL * D3];       // 12 MB, tf32-rounded w_qkv
__device__ float g_wp[(size_t)D_MODEL * D_MODEL];  //  4 MB, tf32-rounded w_proj

__device__ __forceinline__ uint32_t f2tf(float f) {
    uint32_t u;
    asm("cvt.rna.tf32.f32 %0, %1;" : "=r"(u) : "f"(f));
    return u;
}

__device__ __forceinline__ void cp16(uint32_t s, const void* g) {
    asm volatile("cp.async.cg.shared.global [%0], [%1], 16;" :: "r"(s), "l"(g));
}

__device__ __forceinline__ void mma_tf32(float* c, const uint32_t* a,
                                         uint32_t b0, uint32_t b1) {
    asm volatile(
        "mma.sync.aligned.m16n8k8.row.col.f32.tf32.tf32.f32 "
        "{%0,%1,%2,%3}, {%4,%5,%6,%7}, {%8,%9}, {%0,%1,%2,%3};"
        : "+f"(c[0]), "+f"(c[1]), "+f"(c[2]), "+f"(c[3])
        : "r"(a[0]), "r"(a[1]), "r"(a[2]), "r"(a[3]), "r"(b0), "r"(b1));
}

// ---------------------------------------------------------------------------
// Prep: round fp32 -> tf32-in-fp32 (idempotent; makes cp.async staging
// bit-identical to per-element cvt staging).
// ---------------------------------------------------------------------------
__global__ void tf32_round_kernel(const float4* __restrict__ in,
                                  float4* __restrict__ out, int n4) {
    int i = blockIdx.x * blockDim.x + threadIdx.x;
    if (i < n4) {
        float4 v = in[i];
        v.x = __uint_as_float(f2tf(v.x));
        v.y = __uint_as_float(f2tf(v.y));
        v.z = __uint_as_float(f2tf(v.z));
        v.w = __uint_as_float(f2tf(v.w));
        out[i] = v;
    }
}

// ---------------------------------------------------------------------------
// TF32 tensor-core GEMM, cp.async 4-stage pipeline.
// C[M,N] = A[M,K] @ B[K,N]; A,B pre-truncated to tf32. Block 128x128x16,
// 256 threads, warp tile 64x32. No cvt / no register staging in the loop.
// CVT_OUT: round the output to tf32 (for tensors consumed by later mma).
// ---------------------------------------------------------------------------
#define BM 128
#define BN 128
#define BKT 16
#define ASTRIDE (BKT + 4)   /* 20  -> A-frag LDS conflict-free */
#define BSTRIDE (BN + 8)    /* 136 -> B-frag LDS conflict-free */
#define AS_W (BM * ASTRIDE) /* 2560 words */
#define BS_W (BKT * BSTRIDE)/* 2176 words */
#define GSTAGES 4
#define GEMM_SMEM_BYTES (GSTAGES * (AS_W + BS_W) * 4)  /* 75776 */

template <bool CVT_OUT>
__global__ __launch_bounds__(256)
void gemm_tf32_ca(const float* __restrict__ A, const float* __restrict__ B,
                  float* __restrict__ C, int M, int N, int K) {
    extern __shared__ uint32_t ds[];

    const int tid   = threadIdx.x;
    const int warp  = tid >> 5;
    const int lane  = tid & 31;
    const int wm    = warp >> 2;
    const int wn    = warp & 3;
    const int group = lane >> 2;
    const int tig   = lane & 3;
    const int rowBase = blockIdx.y * BM;
    const int colBase = blockIdx.x * BN;
    const int mBase = wm * 64;
    const int nBase = wn * 32;

    // cp.async mapping: 2 x 16B for A, 2 x 16B for B per thread per tile
    const int c0 = tid, c1 = tid + 256;
    const int ar0 = c0 >> 2, ac0 = (c0 & 3) << 2;
    const int ar1 = c1 >> 2, ac1 = (c1 & 3) << 2;
    const int br0 = c0 >> 5, bc0 = (c0 & 31) << 2;
    const int br1 = c1 >> 5, bc1 = (c1 & 31) << 2;

    const float* Ag0 = A + (size_t)(rowBase + ar0) * K + ac0;
    const float* Ag1 = A + (size_t)(rowBase + ar1) * K + ac1;
    const float* Bg0 = B + (size_t)br0 * N + colBase + bc0;
    const float* Bg1 = B + (size_t)br1 * N + colBase + bc1;

    const uint32_t sbase = (uint32_t)__cvta_generic_to_shared(ds);
    const uint32_t sa0 = sbase + (ar0 * ASTRIDE + ac0) * 4;
    const uint32_t sa1 = sbase + (ar1 * ASTRIDE + ac1) * 4;
    const uint32_t sb0 = sbase + (GSTAGES * AS_W + br0 * BSTRIDE + bc0) * 4;
    const uint32_t sb1 = sbase + (GSTAGES * AS_W + br1 * BSTRIDE + bc1) * 4;

    auto issue = [&](int t, int s) {
        cp16(sa0 + s * (AS_W * 4), Ag0 + t * BKT);
        cp16(sa1 + s * (AS_W * 4), Ag1 + t * BKT);
        cp16(sb0 + s * (BS_W * 4), Bg0 + (size_t)t * BKT * N);
        cp16(sb1 + s * (BS_W * 4), Bg1 + (size_t)t * BKT * N);
        asm volatile("cp.async.commit_group;");
    };

    float acc[4][4][4];
    #pragma unroll
    for (int mi = 0; mi < 4; mi++)
        #pragma unroll
        for (int ni = 0; ni < 4; ni++)
            #pragma unroll
            for (int r = 0; r < 4; r++) acc[mi][ni][r] = 0.f;

    const int T = K / BKT;
    issue(0, 0); issue(1, 1); issue(2, 2);

    for (int t = 0; t < T; t++) {
        if (t + 2 < T)      asm volatile("cp.async.wait_group 2;");
        else if (t + 1 < T) asm volatile("cp.async.wait_group 1;");
        else                asm volatile("cp.async.wait_group 0;");
        __syncthreads();   // tile t visible; all warps done with stage (t-1)

        if (t + 3 < T) issue(t + 3, (t + 3) & 3);

        const uint32_t* Asb = ds + (t & 3) * AS_W;
        const uint32_t* Bsb = ds + GSTAGES * AS_W + (t & 3) * BS_W;

        #pragma unroll
        for (int ks = 0; ks < 2; ks++) {
            const int k0 = ks * 8;
            uint32_t a[4][4];
            #pragma unroll
            for (int mi = 0; mi < 4; mi++) {
                int r0 = mBase + mi * 16 + group;
                a[mi][0] = Asb[(r0    ) * ASTRIDE + k0 + tig    ];
                a[mi][1] = Asb[(r0 + 8) * ASTRIDE + k0 + tig    ];
                a[mi][2] = Asb[(r0    ) * ASTRIDE + k0 + tig + 4];
                a[mi][3] = Asb[(r0 + 8) * ASTRIDE + k0 + tig + 4];
            }
            #pragma unroll
            for (int ni = 0; ni < 4; ni++) {
                uint32_t b0 = Bsb[(k0 + tig    ) * BSTRIDE + nBase + ni * 8 + group];
                uint32_t b1 = Bsb[(k0 + tig + 4) * BSTRIDE + nBase + ni * 8 + group];
                #pragma unroll
                for (int mi = 0; mi < 4; mi++)
                    mma_tf32(acc[mi][ni], a[mi], b0, b1);
            }
        }
    }

    #pragma unroll
    for (int mi = 0; mi < 4; mi++) {
        int r0 = rowBase + mBase + mi * 16 + group;
        #pragma unroll
        for (int ni = 0; ni < 4; ni++) {
            int cc = colBase + nBase + ni * 8 + tig * 2;
            float2 v0 = make_float2(acc[mi][ni][0], acc[mi][ni][1]);
            float2 v1 = make_float2(acc[mi][ni][2], acc[mi][ni][3]);
            if (CVT_OUT) {
                v0.x = __uint_as_float(f2tf(v0.x));
                v0.y = __uint_as_float(f2tf(v0.y));
                v1.x = __uint_as_float(f2tf(v1.x));
                v1.y = __uint_as_float(f2tf(v1.y));
            }
            *(float2*)&C[(size_t)r0 * N + cc] = v0;
            *(float2*)&C[(size_t)(r0 + 8) * N + cc] = v1;
        }
    }
}

// ---------------------------------------------------------------------------
// TF32 flash attention, cp.async double-buffered K/V.
// g_qkv is pre-truncated tf32 -> staging is a raw byte copy; the 1/8 scale
// (exact pow2) is applied at the Q fragment load. Numerics identical to R11.
// SMEM: Kt[2][64*68] | Vt[2][64*68] | QP[128*72]  = 106496 B (2 CTA/SM)
// ---------------------------------------------------------------------------
#define KT_W (64 * 68)
#define ATT_QP_OFF (4 * KT_W)
#define ATT_SMEM_BYTES ((4 * KT_W + 128 * 72) * 4)   /* 106496 */

__global__ __launch_bounds__(256)
void attn_tc_kernel() {
    extern __shared__ uint32_t smem[];
    float* QPf = (float*)(smem + ATT_QP_OFF);

    const int tid   = threadIdx.x;
    const int warp  = tid >> 5;
    const int lane  = tid & 31;
    const int group = lane >> 2;
    const int tig   = lane & 3;
    const int b     = blockIdx.z;
    const int h     = blockIdx.y;
    const int q0    = blockIdx.x * 128;

    const uint32_t sbase = (uint32_t)__cvta_generic_to_shared(smem);

    auto issue_kv = [&](int kt, int bf) {
        const float* kb = g_qkv + (size_t)(b * SEQ + kt) * D3 + D_MODEL + h * D_HEAD;
        const uint32_t ksm = sbase + bf * (KT_W * 4);
        const uint32_t vsm = sbase + (2 * KT_W + bf * KT_W) * 4;
        #pragma unroll
        for (int i = 0; i < 4; i++) {
            int u = tid + 256 * i;           // 0..1023
            int r = u >> 4, cc = (u & 15) << 2;
            const float* g = kb + (size_t)r * D3 + cc;
            uint32_t off = (r * 68 + cc) * 4;
            cp16(ksm + off, g);              // K
            cp16(vsm + off, g + D_MODEL);    // V
        }
        asm volatile("cp.async.commit_group;");
    };

    // prologue: start K/V tile 0 immediately, then stage Q
    issue_kv(0, 0);
    #pragma unroll
    for (int i = 0; i < 8; i++) {
        int u = tid + 256 * i;
        int r = u >> 4, c = (u & 15) << 2;
        float4 v4 = *(const float4*)&g_qkv[(size_t)(b * SEQ + q0 + r) * D3 + h * D_HEAD + c];
        *(float4*)&QPf[r * 72 + c] = v4;
    }
    __syncthreads();

    // Q fragments: pre-truncated tf32 * exact pow2 scale -> still tf32
    uint32_t qa[8][4];
    {
        const int r0 = warp * 16 + group;
        #pragma unroll
        for (int ks = 0; ks < 8; ks++) {
            qa[ks][0] = __float_as_uint(0.125f * QPf[(r0    ) * 72 + ks * 8 + tig    ]);
            qa[ks][1] = __float_as_uint(0.125f * QPf[(r0 + 8) * 72 + ks * 8 + tig    ]);
            qa[ks][2] = __float_as_uint(0.125f * QPf[(r0    ) * 72 + ks * 8 + tig + 4]);
            qa[ks][3] = __float_as_uint(0.125f * QPf[(r0 + 8) * 72 + ks * 8 + tig + 4]);
        }
    }

    uint32_t* Pw = smem + ATT_QP_OFF + warp * 16 * 72;   // warp-private P slab

    float oacc[8][4];
    #pragma unroll
    for (int nf = 0; nf < 8; nf++)
        #pragma unroll
        for (int j = 0; j < 4; j++) oacc[nf][j] = 0.f;
    float m0 = -1e30f, m1 = -1e30f, l0 = 0.f, l1 = 0.f;

    int buf = 0;
    const int NT = SEQ / 64;
    for (int t = 0; t < NT; t++) {
        asm volatile("cp.async.wait_group 0;");
        __syncthreads();   // tile t visible; all warps done reading buf^1

        if (t + 1 < NT) issue_kv((t + 1) * 64, buf ^ 1);

        const uint32_t* Ktb = smem + buf * KT_W;
        const uint32_t* Vtb = smem + 2 * KT_W + buf * KT_W;

        // ---- S = Q @ K^T ----
        float sacc[8][4];
        #pragma unroll
        for (int nf = 0; nf < 8; nf++)
            #pragma unroll
            for (int j = 0; j < 4; j++) sacc[nf][j] = 0.f;

        #pragma unroll
        for (int ks = 0; ks < 8; ks++) {
            #pragma unroll
            for (int nf = 0; nf < 8; nf++) {
                uint32_t b0 = Ktb[(nf * 8 + group) * 68 + ks * 8 + tig    ];
                uint32_t b1 = Ktb[(nf * 8 + group) * 68 + ks * 8 + tig + 4];
                mma_tf32(sacc[nf], qa[ks], b0, b1);
            }
        }

        // ---- online softmax ----
        float mx0 = -1e30f, mx1 = -1e30f;
        #pragma unroll
        for (int nf = 0; nf < 8; nf++) {
            mx0 = fmaxf(mx0, fmaxf(sacc[nf][0], sacc[nf][1]));
            mx1 = fmaxf(mx1, fmaxf(sacc[nf][2], sacc[nf][3]));
        }
        mx0 = fmaxf(mx0, __shfl_xor_sync(0xffffffffu, mx0, 1));
        mx0 = fmaxf(mx0, __shfl_xor_sync(0xffffffffu, mx0, 2));
        mx1 = fmaxf(mx1, __shfl_xor_sync(0xffffffffu, mx1, 1));
        mx1 = fmaxf(mx1, __shfl_xor_sync(0xffffffffu, mx1, 2));

        float mn0 = fmaxf(m0, mx0), mn1 = fmaxf(m1, mx1);
        float c0 = __expf(m0 - mn0), c1 = __expf(m1 - mn1);
        l0 *= c0; l1 *= c1;
        #pragma unroll
        for (int nf = 0; nf < 8; nf++) {
            oacc[nf][0] *= c0; oacc[nf][1] *= c0;
            oacc[nf][2] *= c1; oacc[nf][3] *= c1;
        }

        float ps0 = 0.f, ps1 = 0.f;
        #pragma unroll
        for (int nf = 0; nf < 8; nf++) {
            float p0 = __expf(sacc[nf][0] - mn0);
            float p1 = __expf(sacc[nf][1] - mn0);
            float p2 = __expf(sacc[nf][2] - mn1);
            float p3 = __expf(sacc[nf][3] - mn1);
            ps0 += p0 + p1; ps1 += p2 + p3;
            uint32_t* pr0 = &Pw[(group    ) * 72 + nf * 8 + tig * 2];
            uint32_t* pr1 = &Pw[(group + 8) * 72 + nf * 8 + tig * 2];
            pr0[0] = f2tf(p0); pr0[1] = f2tf(p1);
            pr1[0] = f2tf(p2); pr1[1] = f2tf(p3);
        }
        ps0 += __shfl_xor_sync(0xffffffffu, ps0, 1);
        ps0 += __shfl_xor_sync(0xffffffffu, ps0, 2);
        ps1 += __shfl_xor_sync(0xffffffffu, ps1, 1);
        ps1 += __shfl_xor_sync(0xffffffffu, ps1, 2);
        l0 += ps0; l1 += ps1;
        m0 = mn0; m1 = mn1;
        __syncwarp();

        // ---- O += P @ V ----
        #pragma unroll
        for (int ks = 0; ks < 8; ks++) {
            uint32_t pa[4];
            pa[0] = Pw[(group    ) * 72 + ks * 8 + tig    ];
            pa[1] = Pw[(group + 8) * 72 + ks * 8 + tig    ];
            pa[2] = Pw[(group    ) * 72 + ks * 8 + tig + 4];
            pa[3] = Pw[(group + 8) * 72 + ks * 8 + tig + 4];
            #pragma unroll
            for (int nf = 0; nf < 8; nf++) {
                uint32_t b0 = Vtb[(ks * 8 + tig    ) * 68 + nf * 8 + group];
                uint32_t b1 = Vtb[(ks * 8 + tig + 4) * 68 + nf * 8 + group];
                mma_tf32(oacc[nf], pa, b0, b1);
            }
        }
        buf ^= 1;
    }

    // ---- epilogue: normalize, truncate to tf32 (proj input), store ----
    const float inv0 = 1.f / l0, inv1 = 1.f / l1;
    const int r0 = b * SEQ + q0 + warp * 16 + group;
    #pragma unroll
    for (int nf = 0; nf < 8; nf++) {
        int cc = h * D_HEAD + nf * 8 + tig * 2;
        float2 v0 = make_float2(__uint_as_float(f2tf(oacc[nf][0] * inv0)),
                                __uint_as_float(f2tf(oacc[nf][1] * inv0)));
        float2 v1 = make_float2(__uint_as_float(f2tf(oacc[nf][2] * inv1)),
                                __uint_as_float(f2tf(oacc[nf][3] * inv1)));
        *(float2*)&g_attn[(size_t)r0 * D_MODEL + cc] = v0;
        *(float2*)&g_attn[(size_t)(r0 + 8) * D_MODEL + cc] = v1;
    }
}

extern "C" void kernel_launch(void* const* d_in, const int* in_sizes, int n_in,
                              void* d_out, int out_size) {
    const float* x      = (const float*)d_in[0];  // [4,2048,1024]
    const float* w_qkv  = (const float*)d_in[1];  // [1024,3072]
    const float* w_proj = (const float*)d_in[2];  // [1024,1024]
    float* out = (float*)d_out;                   // [4,2048,1024]

    float *qkv_p, *attn_p, *xr_p, *wq_p, *wp_p;
    cudaGetSymbolAddress((void**)&qkv_p,  g_qkv);
    cudaGetSymbolAddress((void**)&attn_p, g_attn);
    cudaGetSymbolAddress((void**)&xr_p,   g_xr);
    cudaGetSymbolAddress((void**)&wq_p,   g_wq);
    cudaGetSymbolAddress((void**)&wp_p,   g_wp);

    cudaFuncSetAttribute(gemm_tf32_ca<true>,
                         cudaFuncAttributeMaxDynamicSharedMemorySize, GEMM_SMEM_BYTES);
    cudaFuncSetAttribute(gemm_tf32_ca<false>,
                         cudaFuncAttributeMaxDynamicSharedMemorySize, GEMM_SMEM_BYTES);
    cudaFuncSetAttribute(attn_tc_kernel,
                         cudaFuncAttributeMaxDynamicSharedMemorySize, ATT_SMEM_BYTES);

    // 0) pre-truncate inputs to tf32 (idempotent; enables raw cp.async staging)
    tf32_round_kernel<<<(M_TOK * D_MODEL / 4 + 255) / 256, 256>>>(
        (const float4*)x, (float4*)xr_p, M_TOK * D_MODEL / 4);
    tf32_round_kernel<<<(D_MODEL * D3 / 4 + 255) / 256, 256>>>(
        (const float4*)w_qkv, (float4*)wq_p, D_MODEL * D3 / 4);
    tf32_round_kernel<<<(D_MODEL * D_MODEL / 4 + 255) / 256, 256>>>(
        (const float4*)w_proj, (float4*)wp_p, D_MODEL * D_MODEL / 4);

    // 1) QKV = X @ W_qkv  (outputs tf32-rounded for attention)
    gemm_tf32_ca<true><<<dim3(D3 / BN, M_TOK / BM), 256, GEMM_SMEM_BYTES>>>(
        xr_p, wq_p, qkv_p, M_TOK, D3, D_MODEL);

    // 2) flash attention (outputs tf32-rounded for proj)
    attn_tc_kernel<<<dim3(SEQ / 128, N_HEADS, BATCH), 256, ATT_SMEM_BYTES>>>();

    // 3) out = attn @ W_proj (plain fp32 output)
    gemm_tf32_ca<false><<<dim3(D_MODEL / BN, M_TOK / BM), 256, GEMM_SMEM_BYTES>>>(
        attn_p, wp_p, out, M_TOK, D_MODEL, D_MODEL);
}